// round 8
// baseline (speedup 1.0000x reference)
#include <cuda_runtime.h>
#include <math_constants.h>

#define NBOX   10647          // 52*52*3 + 26*26*3 + 13*13*3
#define NBATCH 4
#define DET_ELEMS (NBATCH*NBOX*6)
#define CAP    256            // per-(batch,class) bucket capacity (mean ~66, >20 sigma safe)

#define THREADS 128
#define GRID    640           // = NBATCH*80*2 NMS tasks; decode uses first 96 blocks
#define QTOT    845           // float4-quads over scale1+scale2 spatial (676 + 169)
#define DEC_QUAD  (3*NBATCH*QTOT)     // 10140 quad threads (scales 1,2)
#define DEC_TOTAL (DEC_QUAD + 3*NBATCH*169)  // + 2028 scalar threads (scale 3) = 12168

// Scratch (__device__ globals — zero-initialized at load; kernel restores zeros each call)
__device__ int   g_cnt [NBATCH*80];          // read+reset by NMS sub-block 0
__device__ int   g_cnt2[NBATCH*80];          // mirror; read+reset by NMS sub-block 1
__device__ float g_bucket[NBATCH*80*CAP*8];  // b0,b1,b2,b3 | area,conf,idx,pad
__device__ volatile int g_arrive;
__device__ int   g_done;

__constant__ float c_anch[3][3][2] = {
  {{10.f,13.f},{16.f,30.f},{33.f,23.f}},
  {{30.f,61.f},{62.f,45.f},{59.f,119.f}},
  {{116.f,90.f},{156.f,198.f},{373.f,326.f}}
};

__device__ __forceinline__ float sigmoidf_(float x){ return 1.0f/(1.0f + expf(-x)); }

// Full per-box epilogue: reference math (same op order), det/keep stores, bucket append.
__device__ __forceinline__ void emit_box(
    float tx, float ty, float tw, float th, float tc,
    int s, int W, float stride, int si, int a, int b, int bi, int nbase,
    float* __restrict__ det_out, float* __restrict__ keep_out)
{
    int h = s / W, w = s - h*W;
    float x  = (sigmoidf_(tx) + (float)w) * stride;
    float y  = (sigmoidf_(ty) + (float)h) * stride;
    float bw = expf(tw) * c_anch[si][a][0] * stride;
    float bh = expf(th) * c_anch[si][a][1] * stride;
    float conf = sigmoidf_(tc);

    float b0 = x - bw*0.5f, b1 = x + bw*0.5f;   // both from x (reference quirk)
    float b2 = y - bh*0.5f, b3 = y + bh*0.5f;   // both from y
    float area = fmaxf(b2-b0+1.0f, 0.0f) * fmaxf(b3-b1+1.0f, 0.0f);

    int n = nbase + (w*W + h)*3 + a;            // reference flatten order (W==H)
    long o = (long)b*NBOX + n;
    float* dp = det_out + o*6;
    dp[0]=b0; dp[1]=b1; dp[2]=b2; dp[3]=b3; dp[4]=conf; dp[5]=(float)bi;
    keep_out[o] = 0.0f;                          // NMS overwrites valid boxes

    if (conf > 0.5f){
        int bc = b*80 + bi;
        int pos = atomicAdd(&g_cnt[bc], 1);
        atomicAdd(&g_cnt2[bc], 1);               // mirror for 2nd NMS sub-block
        if (pos < CAP){
            float4* rec = (float4*)(g_bucket + ((long)bc*CAP + pos)*8);
            rec[0] = make_float4(b0, b1, b2, b3);
            rec[1] = make_float4(area, conf, (float)n, 0.0f);
        }
    }
}

// Fused decode + device-wide barrier + NMS. 640 blocks x 128 threads;
// __launch_bounds__(128,5): capacity 148*5=740 resident blocks > 640 -> barrier safe.
__global__ void __launch_bounds__(THREADS, 5)
fused_kernel(const float* __restrict__ f1,
             const float* __restrict__ f2,
             const float* __restrict__ f3,
             float* __restrict__ det_out,
             float* __restrict__ keep_out){
    __shared__ float4 s_lo[CAP];     // b0,b1,b2,b3
    __shared__ float2 s_ac[CAP];     // area, conf
    __shared__ int    s_idx[CAP];

    // ---------------- Phase 1: decode ----------------
    int T = blockIdx.x*THREADS + threadIdx.x;
    if (T < DEC_QUAD){
        // Quad path (scales 1,2): one thread decodes 4 consecutive spatial cells
        // with 85 independent LDG.128 (HW%4==0 -> full quads, 16B aligned).
        int a = T / (NBATCH*QTOT);
        int r = T - a*(NBATCH*QTOT);
        int b = r / QTOT;
        int q = r - b*QTOT;
        const float* feat; int W; float stride; int nbase; int HW; int si; int s4;
        if (q < 676){ feat=f1; W=52; stride=8.0f;  nbase=0;    HW=2704; si=0; s4=q*4; }
        else        { feat=f2; W=26; stride=16.0f; nbase=8112; HW=676;  si=1; s4=(q-676)*4; }

        const float* fc = feat + ((long)b*255 + a*85)*HW + s4;
        float4 vx = *(const float4*)(fc);
        float4 vy = *(const float4*)(fc + HW);
        float4 vw = *(const float4*)(fc + 2*HW);
        float4 vh = *(const float4*)(fc + 3*HW);
        float4 vc = *(const float4*)(fc + 4*HW);

        // Streaming argmax over 80 classes, e increasing + strict '>' ->
        // exact first-occurrence argmax (sigmoid monotone, so raw logits OK).
        const float* fcls = fc + 5L*HW;
        float4 best = *(const float4*)(fcls);
        int bi0=0, bi1=0, bi2=0, bi3=0;
        #pragma unroll 4
        for (int e = 1; e < 80; e++){
            float4 v = *(const float4*)(fcls + (long)e*HW);
            if (v.x > best.x){ best.x = v.x; bi0 = e; }
            if (v.y > best.y){ best.y = v.y; bi1 = e; }
            if (v.z > best.z){ best.z = v.z; bi2 = e; }
            if (v.w > best.w){ best.w = v.w; bi3 = e; }
        }
        emit_box(vx.x,vy.x,vw.x,vh.x,vc.x, s4+0, W, stride, si,a,b, bi0, nbase, det_out, keep_out);
        emit_box(vx.y,vy.y,vw.y,vh.y,vc.y, s4+1, W, stride, si,a,b, bi1, nbase, det_out, keep_out);
        emit_box(vx.z,vy.z,vw.z,vh.z,vc.z, s4+2, W, stride, si,a,b, bi2, nbase, det_out, keep_out);
        emit_box(vx.w,vy.w,vw.w,vh.w,vc.w, s4+3, W, stride, si,a,b, bi3, nbase, det_out, keep_out);
    }
    else if (T < DEC_TOTAL){
        // Scalar path (scale 3, HW=169: odd -> no aligned float4). One thread per box.
        int idx = T - DEC_QUAD;
        int a = idx / (NBATCH*169);
        int r = idx - a*(NBATCH*169);
        int b = r / 169;
        int s = r - b*169;
        const float* fc = f3 + ((long)b*255 + a*85)*169 + s;
        float tx = fc[0], ty = fc[169], tw = fc[338], th = fc[507], tc = fc[676];
        const float* fcls = fc + 5*169;
        float best = fcls[0]; int bi = 0;
        #pragma unroll 8
        for (int e = 1; e < 80; e++){
            float v = fcls[e*169];
            if (v > best){ best = v; bi = e; }
        }
        emit_box(tx,ty,tw,th,tc, s, 13, 32.0f, 2, a, b, bi, 10140, det_out, keep_out);
    }

    // ---------------- Device-wide barrier ----------------
    __threadfence();                                 // publish stores before arriving
    __syncthreads();
    if (threadIdx.x == 0){
        atomicAdd((int*)&g_arrive, 1);
        while (g_arrive < GRID) __nanosleep(64);     // all 640 blocks spin here
    }
    __syncthreads();
    __threadfence();                                 // acquire side

    // ---------------- Phase 2: NMS (two sub-blocks per bucket) ----------------
    int bid  = blockIdx.x;
    int bc   = bid >> 1;                             // b*80 + c
    int sblk = bid & 1;
    int b    = bc / 80;
    int t    = threadIdx.x;

    int* myCnt = sblk ? &g_cnt2[bc] : &g_cnt[bc];
    int cnt = *myCnt; if (cnt > CAP) cnt = CAP;
    int cntPad = (cnt + 31) & ~31;

    const float4* base = (const float4*)(g_bucket + (long)bc*CAP*8);
    for (int i = t; i < cntPad; i += THREADS){
        if (i < cnt){
            float4 lo = base[2*i], hi = base[2*i+1];
            s_lo[i] = lo;
            s_ac[i] = make_float2(hi.x, hi.y);
            s_idx[i] = (int)hi.z;
        } else {
            s_lo[i] = make_float4(0.f,0.f,0.f,0.f);
            s_ac[i] = make_float2(0.f, -CUDART_INF_F);   // sentinel: never a suppressor
        }
    }
    __syncthreads();
    if (t == 0) *myCnt = 0;                          // restore zero for next call

    int warp = t >> 5, lane = t & 31;
    for (int i = sblk*(THREADS/32) + warp; i < cnt; i += 2*(THREADS/32)){
        float4 il = s_lo[i];                         // warp-uniform broadcast
        float2 ia = s_ac[i];
        bool found = false;
        for (int j0 = 0; j0 < cntPad; j0 += 32){
            int j = j0 + lane;                       // always in-bounds (padded)
            float4 jl = s_lo[j];
            float2 ja = s_ac[j];
            bool p = false;
            if (ia.y < ja.y){                        // conf_i < conf_j (kills pads & j==i)
                float wI = fmaxf(fminf(il.z, jl.z) - fmaxf(il.x, jl.x) + 1.0f, 0.0f);
                float hI = fmaxf(fminf(il.w, jl.w) - fmaxf(il.y, jl.y) + 1.0f, 0.0f);
                float inter = wI * hI;
                float uni = ia.x + ja.x - inter;     // same op order as reference
                float thr = 0.4f * uni;
                if (inter > thr*0.9999f)             // certainly-false cut
                    p = (inter > thr*1.0001f) ? true // certainly-true cut
                        : (inter / uni > 0.4f);      // exact IEEE div inside the band
            }
            if (__any_sync(0xFFFFFFFFu, p)){ found = true; break; }
        }
        if (lane == 0)
            keep_out[(long)b*NBOX + s_idx[i]] = found ? 1.0f : 0.0f;
    }

    // ---------------- Epilogue: restore barrier counters ----------------
    __syncthreads();
    if (t == 0){
        int d = atomicAdd(&g_done, 1);
        if (d == GRID - 1){                          // last finisher: all blocks passed spin
            g_done = 0;
            *(int*)&g_arrive = 0;
        }
    }
}

extern "C" void kernel_launch(void* const* d_in, const int* in_sizes, int n_in,
                              void* d_out, int out_size){
    const float* f1 = (const float*)d_in[0];   // (4,255,52,52)
    const float* f2 = (const float*)d_in[1];   // (4,255,26,26)
    const float* f3 = (const float*)d_in[2];   // (4,255,13,13)
    float* det  = (float*)d_out;               // (4,10647,6) then keep (4,10647)
    float* keep = det + DET_ELEMS;

    fused_kernel<<<GRID, THREADS>>>(f1, f2, f3, det, keep);
}